// round 6
// baseline (speedup 1.0000x reference)
#include <cuda_runtime.h>
#include <cstdint>
#include <cstddef>

#define CIN   2112
#define COUT  192
#define NB    256
#define HW    49
#define NP    56          // padded columns per batch (7 n8-tiles)
#define G     2           // batches per block
#define KT    16          // K per tile (2 k8 steps)
#define NITER (CIN / KT)  // 132
#define AS_STRIDE 20      // As row stride (floats), conflict-free both ways
#define THREADS 256

// Scratch (alloc-free rules): precomputed BN affine + tf32-rounded W
__device__ float g_scale[CIN];
__device__ float g_shift[CIN];
__device__ __align__(16) float g_W[COUT * CIN];

__device__ __forceinline__ uint32_t f2tf32(float f) {
    uint32_t t;
    asm("cvt.rna.tf32.f32 %0, %1;" : "=r"(t) : "f"(f));
    return t;
}

__global__ void prep_kernel(const float* __restrict__ gamma,
                            const float* __restrict__ beta,
                            const float* __restrict__ rmean,
                            const float* __restrict__ rvar,
                            const float* __restrict__ W) {
    int i = blockIdx.x * blockDim.x + threadIdx.x;
    if (i < CIN) {
        float inv = rsqrtf(rvar[i] + 1e-5f);
        float sc  = gamma[i] * inv;
        g_scale[i] = sc;
        g_shift[i] = beta[i] - rmean[i] * sc;
    }
    const int total = COUT * CIN;
    for (int j = i; j < total; j += gridDim.x * blockDim.x) {
        g_W[j] = __uint_as_float(f2tf32(W[j]));
    }
}

__device__ __forceinline__ void cp_async16(uint32_t dst_smem, const void* src) {
    asm volatile("cp.async.cg.shared.global [%0], [%1], 16;\n" :: "r"(dst_smem), "l"(src));
}

__device__ __forceinline__ void mma_tf32(float* d, const uint32_t* a, uint32_t b0, uint32_t b1) {
    asm volatile(
        "mma.sync.aligned.m16n8k8.row.col.f32.tf32.tf32.f32 "
        "{%0,%1,%2,%3}, {%4,%5,%6,%7}, {%8,%9}, {%0,%1,%2,%3};\n"
        : "+f"(d[0]), "+f"(d[1]), "+f"(d[2]), "+f"(d[3])
        : "r"(a[0]), "r"(a[1]), "r"(a[2]), "r"(a[3]), "r"(b0), "r"(b1));
}

__global__ __launch_bounds__(THREADS, 1)
void gemm_kernel(const float* __restrict__ x, float* __restrict__ out) {
    __shared__ __align__(16) uint32_t As[2][COUT * AS_STRIDE];   // W tiles: [m][k], tf32 bits
    __shared__ __align__(16) uint32_t Bs[2][G * KT * NP];        // h tiles: [g*16+kr][col], tf32 bits

    const int tid  = threadIdx.x;
    const int lane = tid & 31;
    const int w    = tid >> 5;
    const int gr   = lane >> 2;   // group id (0..7)
    const int ct   = lane & 3;    // thread-in-group (0..3)
    const int wm   = w >> 1;      // m-quarter 0..3
    const int wg   = w & 1;       // batch within group
    const int batch0 = blockIdx.x * G;

    // ---- per-thread x-load geometry (kt-invariant) ----
    int        ld_kr[7], ld_sidx[7];
    const float* ld_ptr[7];
    bool       ld_ok[7];
    #pragma unroll
    for (int i = 0; i < 7; i++) {
        int idx = tid + i * THREADS;       // 0..1791
        int row = idx / NP;                // 0..31 == g*16 + kr
        int col = idx % NP;
        int g   = row >> 4;
        int kr  = row & 15;
        ld_kr[i]   = kr;
        ld_sidx[i] = row * NP + col;
        ld_ok[i]   = (col < HW);
        ld_ptr[i]  = x + ((size_t)(batch0 + g) * CIN + kr) * HW + col;
    }

    float acc[3][7][4];
    #pragma unroll
    for (int i = 0; i < 3; i++)
        #pragma unroll
        for (int j = 0; j < 7; j++)
            #pragma unroll
            for (int q = 0; q < 4; q++) acc[i][j][q] = 0.0f;

    float xr[7];

    // ---- helpers as lambdas ----
    auto fillAs = [&](int p, int kt) {
        const float* wb = g_W + kt * KT;
        #pragma unroll
        for (int i = 0; i < 3; i++) {
            int o = tid + i * THREADS;   // 0..767
            int m = o >> 2;
            int s = o & 3;
            uint32_t dst = (uint32_t)__cvta_generic_to_shared(&As[p][m * AS_STRIDE + s * 4]);
            cp_async16(dst, wb + (size_t)m * CIN + s * 4);
        }
    };
    auto loadX = [&](int kt) {
        const int off = kt * KT * HW;
        #pragma unroll
        for (int i = 0; i < 7; i++)
            xr[i] = ld_ok[i] ? __ldg(ld_ptr[i] + off) : 0.0f;
    };
    auto stsB = [&](int p, int kt) {
        const int k0 = kt * KT;
        #pragma unroll
        for (int i = 0; i < 7; i++) {
            uint32_t t = 0u;
            if (ld_ok[i]) {
                int c = k0 + ld_kr[i];
                float h = fmaxf(fmaf(xr[i], __ldg(g_scale + c), __ldg(g_shift + c)), 0.0f);
                t = f2tf32(h);
            }
            Bs[p][ld_sidx[i]] = t;
        }
    };
    auto computeTile = [&](int p) {
        const uint32_t* asp = As[p];
        const uint32_t* bsp = Bs[p] + wg * (KT * NP);
        #pragma unroll
        for (int kk = 0; kk < 2; kk++) {
            const int kb = kk * 8;
            uint32_t a[3][4];
            #pragma unroll
            for (int i = 0; i < 3; i++) {
                int m = wm * 48 + i * 16;
                a[i][0] = asp[(m + gr)     * AS_STRIDE + kb + ct];
                a[i][1] = asp[(m + gr + 8) * AS_STRIDE + kb + ct];
                a[i][2] = asp[(m + gr)     * AS_STRIDE + kb + ct + 4];
                a[i][3] = asp[(m + gr + 8) * AS_STRIDE + kb + ct + 4];
            }
            #pragma unroll
            for (int j = 0; j < 7; j++) {
                uint32_t b0 = bsp[(kb + ct)     * NP + j * 8 + gr];
                uint32_t b1 = bsp[(kb + ct + 4) * NP + j * 8 + gr];
                #pragma unroll
                for (int i = 0; i < 3; i++)
                    mma_tf32(acc[i][j], a[i], b0, b1);
            }
        }
    };

    // ---- pipelined main loop ----
    fillAs(0, 0);
    asm volatile("cp.async.commit_group;\n");
    loadX(0);

    for (int kt = 0; kt < NITER; kt++) {
        const int p = kt & 1;
        stsB(p, kt);
        if (kt + 1 < NITER) {
            fillAs(p ^ 1, kt + 1);
            asm volatile("cp.async.commit_group;\n");
            asm volatile("cp.async.wait_group 1;\n");
        } else {
            asm volatile("cp.async.wait_group 0;\n");
        }
        __syncthreads();
        if (kt + 1 < NITER) loadX(kt + 1);
        computeTile(p);
        __syncthreads();
    }

    // ---- epilogue ----
    const int batch = batch0 + wg;
    float* ob = out + (size_t)batch * COUT * HW;
    #pragma unroll
    for (int i = 0; i < 3; i++) {
        const int m = wm * 48 + i * 16;
        const int r0 = m + gr, r1 = m + gr + 8;
        #pragma unroll
        for (int j = 0; j < 7; j++) {
            const int n0 = j * 8 + 2 * ct;
            if (n0 < HW) {
                ob[r0 * HW + n0] = acc[i][j][0];
                ob[r1 * HW + n0] = acc[i][j][2];
            }
            if (n0 + 1 < HW) {
                ob[r0 * HW + n0 + 1] = acc[i][j][1];
                ob[r1 * HW + n0 + 1] = acc[i][j][3];
            }
        }
    }
}

extern "C" void kernel_launch(void* const* d_in, const int* in_sizes, int n_in,
                              void* d_out, int out_size) {
    const float* x     = (const float*)d_in[0];
    const float* gamma = (const float*)d_in[1];
    const float* beta  = (const float*)d_in[2];
    const float* rmean = (const float*)d_in[3];
    const float* rvar  = (const float*)d_in[4];
    const float* W     = (const float*)d_in[5];
    float* out = (float*)d_out;

    prep_kernel<<<(COUT * CIN + 1023) / 1024, 1024>>>(gamma, beta, rmean, rvar, W);
    gemm_kernel<<<NB / G, THREADS>>>(x, out);
}